// round 17
// baseline (speedup 1.0000x reference)
#include <cuda_runtime.h>
#include <cstdint>

#define B_DIM 8192
#define N_DIM 4096
#define P_DIM 8
#define D_DIM 512

// ---------------- scratch (device globals; referenced ONLY in device code) ----------------
__device__ float g_h[(size_t)B_DIM * N_DIM];    // GEMM1 out, tf32-rounded, k-permuted layout
__device__ float g_xp[(size_t)B_DIM * N_DIM];   // x, tf32-rounded, k-permuted layout
__device__ float g_w1t[(size_t)P_DIM * D_DIM * D_DIM];  // W1^T [e][d-perm], rounded
__device__ float g_w2t[(size_t)P_DIM * D_DIM * D_DIM];  // (diag(s)W2)^T [e][d-perm], rounded
__device__ float g_psum[64 * N_DIM];
__device__ float g_psq[64 * N_DIM];
__device__ float g_s[N_DIM];                    // rstd * bn_weight
__device__ float g_t[N_DIM];                    // bn_bias - mean_acc * s
__device__ float g_bias2f[N_DIM];               // bias2 + t @ W2

// ---------------- tiling ----------------
constexpr int BM = 128;
constexpr int BN = 128;
constexpr int BK = 32;
constexpr int NKT = D_DIM / BK;        // 16
constexpr int STAGES = 3;
constexpr int A_FLOATS = BM * BK;      // 4096 (no pad; XOR swizzle)
constexpr int B_FLOATS = BN * BK;      // 4096
constexpr int STAGE_FLOATS = A_FLOATS + B_FLOATS;     // 8192
constexpr int SMEM_BYTES = STAGES * STAGE_FLOATS * 4; // 98304

__device__ __forceinline__ float fast_sigmoid(float z) {
    return 1.0f / (1.0f + __expf(-z));
}
__device__ __forceinline__ uint32_t smem_u32(const void* p) {
    return (uint32_t)__cvta_generic_to_shared(p);
}
__device__ __forceinline__ void cp_async16(uint32_t dst, const void* src) {
    asm volatile("cp.async.cg.shared.global [%0], [%1], 16;" :: "r"(dst), "l"(src));
}
__device__ __forceinline__ uint32_t to_tf32(float f) {
    uint32_t u;
    asm("cvt.rna.tf32.f32 %0, %1;" : "=r"(u) : "f"(f));
    return u;
}
__device__ __forceinline__ float round_tf32(float f) {
    return __uint_as_float(to_tf32(f));
}
__device__ __forceinline__ void mma_tf32(float& c0, float& c1, float& c2, float& c3,
                                         uint32_t a0, uint32_t a1, uint32_t a2, uint32_t a3,
                                         uint32_t b0, uint32_t b1) {
    asm volatile(
        "mma.sync.aligned.m16n8k8.row.col.f32.tf32.tf32.f32 "
        "{%0,%1,%2,%3},{%4,%5,%6,%7},{%8,%9},{%0,%1,%2,%3};"
        : "+f"(c0), "+f"(c1), "+f"(c2), "+f"(c3)
        : "r"(a0), "r"(a1), "r"(a2), "r"(a3), "r"(b0), "r"(b1));
}

// Both operands pre-rounded + k-permuted (pos = (k%4)*8 + k/4 within 32-chunks),
// smem rows XOR-swizzled by quad: q' = q ^ (row & 7).
// MODE 0: g_h(perm) = x @ bdiag(W1), fused partial column stats  (A=g_xp, B=g_w1t)
// MODE 1: out = gate(g_h @ bdiag(W2') + g_bias2f + x)            (A=g_h,  B=g_w2t)
template <int MODE>
__global__ void __launch_bounds__(256, 2)
gemm_mma(const float* __restrict__ x_res,
         const float* __restrict__ gamma,
         const float* __restrict__ beta,
         float* __restrict__ out)
{
    extern __shared__ __align__(16) float smem[];

    const int tid  = threadIdx.x;
    const int wid  = tid >> 5;
    const int lane = tid & 31;
    const int wm   = wid >> 2;       // 0..1  (64-row slabs)
    const int wn   = wid & 3;        // 0..3  (32-col slabs)
    const int lg   = lane >> 2;      // 0..7
    const int lt   = lane & 3;       // 0..3

    const int ntile = blockIdx.x;    // 0..31
    const int mtile = blockIdx.y;    // 0..63
    const int p     = ntile >> 2;
    const int ecol0 = (ntile & 3) * BN;
    const int row0  = mtile * BM;

    const float* Abase = (MODE == 0 ? (const float*)g_xp : (const float*)g_h)
                       + (size_t)row0 * N_DIM + p * D_DIM;
    const float* Bbase = (MODE == 0 ? (const float*)g_w1t : (const float*)g_w2t)
                       + (size_t)p * D_DIM * D_DIM + (size_t)ecol0 * D_DIM;

    const uint32_t smem_base = smem_u32(smem);

    // cp.async: tile rows of 32 floats = 8 quads; dst quad = q ^ (row & 7)
    auto load_stage = [&](int kt, int buf) {
        const uint32_t a_s = smem_base + (uint32_t)(buf * STAGE_FLOATS) * 4u;
        const uint32_t b_s = a_s + (uint32_t)A_FLOATS * 4u;
        const float* Ag = Abase + kt * BK;
        const float* Bg = Bbase + kt * BK;
        #pragma unroll
        for (int q4 = 0; q4 < 4; q4++) {              // A: 128 rows x 8 quads
            const int idx = q4 * 256 + tid;           // 0..1023
            const int r = idx >> 3, q = idx & 7;
            const int qs = q ^ (r & 7);
            cp_async16(a_s + (uint32_t)(r * 32 + qs * 4) * 4u,
                       Ag + (size_t)r * N_DIM + q * 4);
        }
        #pragma unroll
        for (int q4 = 0; q4 < 4; q4++) {              // B: 128 rows x 8 quads
            const int idx = q4 * 256 + tid;
            const int r = idx >> 3, q = idx & 7;
            const int qs = q ^ (r & 7);
            cp_async16(b_s + (uint32_t)(r * 32 + qs * 4) * 4u,
                       Bg + (size_t)r * D_DIM + q * 4);
        }
        asm volatile("cp.async.commit_group;" ::: "memory");
    };

    float acc[4][4][4];
    #pragma unroll
    for (int i = 0; i < 4; i++)
        #pragma unroll
        for (int j = 0; j < 4; j++)
            #pragma unroll
            for (int k = 0; k < 4; k++) acc[i][j][k] = 0.0f;

    load_stage(0, 0);
    load_stage(1, 1);

    // per-thread constant quad offsets (floats) for the two halves
    const int qa_h0 = (((2 * lt + 0) ^ lg) * 4);
    const int qa_h1 = (((2 * lt + 1) ^ lg) * 4);

    for (int kt = 0; kt < NKT; kt++) {
        if (kt == NKT - 1) asm volatile("cp.async.wait_group 0;" ::: "memory");
        else               asm volatile("cp.async.wait_group 1;" ::: "memory");
        __syncthreads();
        if (kt + 2 < NKT) load_stage(kt + 2, (kt + 2) % STAGES);

        const float* As = smem + (kt % STAGES) * STAGE_FLOATS;
        const float* Bs = As + A_FLOATS;

        #pragma unroll
        for (int h = 0; h < 2; h++) {    // half h covers k8 steps s = 2h, 2h+1
            const int qa = h ? qa_h1 : qa_h0;
            uint4 va[4][2];
            #pragma unroll
            for (int mi = 0; mi < 4; mi++) {
                const int r0 = wm * 64 + mi * 16 + lg;     // r0 % 8 == lg
                va[mi][0] = *(const uint4*)(As + r0 * 32 + qa);
                va[mi][1] = *(const uint4*)(As + (r0 + 8) * 32 + qa);
            }
            uint4 vb[4];
            #pragma unroll
            for (int ni = 0; ni < 4; ni++) {
                const int n = wn * 32 + ni * 8 + lg;       // n % 8 == lg
                vb[ni] = *(const uint4*)(Bs + n * 32 + qa);
            }
            #pragma unroll
            for (int mi = 0; mi < 4; mi++)
                #pragma unroll
                for (int ni = 0; ni < 4; ni++) {
                    // s = 2h : components .x (j=4h), .y (j=4h+1)
                    mma_tf32(acc[mi][ni][0], acc[mi][ni][1], acc[mi][ni][2], acc[mi][ni][3],
                             va[mi][0].x, va[mi][1].x, va[mi][0].y, va[mi][1].y,
                             vb[ni].x, vb[ni].y);
                    // s = 2h+1 : components .z, .w
                    mma_tf32(acc[mi][ni][0], acc[mi][ni][1], acc[mi][ni][2], acc[mi][ni][3],
                             va[mi][0].z, va[mi][1].z, va[mi][0].w, va[mi][1].w,
                             vb[ni].z, vb[ni].w);
                }
        }
    }

    if (MODE == 0) {
        // ---- epilogue: store tf32-rounded h in k-PERMUTED layout + fused stats ----
        float s0[4], q0[4], s1[4], q1[4];
        #pragma unroll
        for (int ni = 0; ni < 4; ni++) { s0[ni] = q0[ni] = s1[ni] = q1[ni] = 0.0f; }

        #pragma unroll
        for (int mi = 0; mi < 4; mi++) {
            #pragma unroll
            for (int ni = 0; ni < 4; ni++) {
                const int pos = ni * 8 + 2 * lt;               // within 32-chunk
                const int pm0 = ((pos & 3) << 3) + (pos >> 2); // perm(pos); perm(pos+1)=pm0+8
                #pragma unroll
                for (int rr = 0; rr < 2; rr++) {
                    const int gr = row0 + wm * 64 + mi * 16 + lg + rr * 8;
                    const float v0 = round_tf32(acc[mi][ni][rr * 2 + 0]);
                    const float v1 = round_tf32(acc[mi][ni][rr * 2 + 1]);
                    float* hp = (float*)g_h + (size_t)gr * N_DIM + ntile * BN + wn * 32;
                    hp[pm0]     = v0;
                    hp[pm0 + 8] = v1;
                    s0[ni] += v0; q0[ni] += v0 * v0;
                    s1[ni] += v1; q1[ni] += v1 * v1;
                }
            }
        }
        #pragma unroll
        for (int ni = 0; ni < 4; ni++) {
            #pragma unroll
            for (int off = 16; off >= 4; off >>= 1) {
                s0[ni] += __shfl_down_sync(0xffffffffu, s0[ni], off);
                q0[ni] += __shfl_down_sync(0xffffffffu, q0[ni], off);
                s1[ni] += __shfl_down_sync(0xffffffffu, s1[ni], off);
                q1[ni] += __shfl_down_sync(0xffffffffu, q1[ni], off);
            }
        }
        __syncthreads();
        float* ps = smem;
        float* pq = smem + 256;
        if (lane < 4) {
            #pragma unroll
            for (int ni = 0; ni < 4; ni++) {
                const int cl = wn * 32 + ni * 8 + 2 * lane;   // UNpermuted column
                ps[wm * 128 + cl]     = s0[ni];
                ps[wm * 128 + cl + 1] = s1[ni];
                pq[wm * 128 + cl]     = q0[ni];
                pq[wm * 128 + cl + 1] = q1[ni];
            }
        }
        __syncthreads();
        if (tid < 128) {
            const size_t o = (size_t)mtile * N_DIM + ntile * BN + tid;
            g_psum[o] = ps[tid] + ps[128 + tid];
            g_psq[o]  = pq[tid] + pq[128 + tid];
        }
        return;
    }

    // ---- MODE 1 epilogue: bias + residual + gate, normal layout ----
    #pragma unroll
    for (int mi = 0; mi < 4; mi++) {
        #pragma unroll
        for (int ni = 0; ni < 4; ni++) {
            const int gc = ntile * BN + wn * 32 + ni * 8 + 2 * lt;
            const float2 b2v = *(const float2*)((const float*)g_bias2f + gc);
            const float2 gm = *(const float2*)(gamma + gc);
            const float2 bt = *(const float2*)(beta + gc);
            #pragma unroll
            for (int rr = 0; rr < 2; rr++) {
                const int gr = row0 + wm * 64 + mi * 16 + lg + rr * 8;
                const size_t gidx = (size_t)gr * N_DIM + gc;
                const float2 xv = *(const float2*)(x_res + gidx);
                float o30 = acc[mi][ni][rr * 2 + 0] + b2v.x + xv.x;
                float o31 = acc[mi][ni][rr * 2 + 1] + b2v.y + xv.y;
                float2 o;
                o.x = (gm.x + fast_sigmoid(bt.x * o30) * (1.0f - gm.x)) * o30;
                o.y = (gm.y + fast_sigmoid(bt.y * o31) * (1.0f - gm.y)) * o31;
                *(float2*)(out + gidx) = o;
            }
        }
    }
}

// ---------------- prep: x -> g_xp (round + k-permute within 32-chunks) ----------------
__global__ void prep_x_kernel(const float* __restrict__ x)
{
    const size_t i = (size_t)blockIdx.x * 256 + threadIdx.x;   // float4 idx
    float4 v = *(const float4*)(x + i * 4);
    const size_t base = (size_t)(i >> 3) * 32;   // 32-float chunk base
    const int qc = (int)(i & 7);                 // quad within chunk; pos = qc*4+t -> t*8+qc
    float* xp = (float*)g_xp;
    xp[base + 0 * 8 + qc] = round_tf32(v.x);
    xp[base + 1 * 8 + qc] = round_tf32(v.y);
    xp[base + 2 * 8 + qc] = round_tf32(v.z);
    xp[base + 3 * 8 + qc] = round_tf32(v.w);
}

// ---------------- prep: W -> Wt [p][e][d-perm], rounded, optionally scaled by g_s[d] ----
template <bool SCALE>
__global__ void prep_w_kernel(const float* __restrict__ w, int which)
{
    __shared__ float tile[32][33];
    const int p  = blockIdx.z;
    const int d0 = blockIdx.x * 32;
    const int e0 = blockIdx.y * 32;
    const int tx = threadIdx.x, ty = threadIdx.y;   // (32, 8)
    const float* wp = w + (size_t)p * D_DIM * D_DIM;
    float* wt = (which == 0 ? (float*)g_w1t : (float*)g_w2t) + (size_t)p * D_DIM * D_DIM;
    #pragma unroll
    for (int i = 0; i < 32; i += 8) {
        float v = wp[(size_t)(d0 + ty + i) * D_DIM + e0 + tx];
        if (SCALE) v *= g_s[p * D_DIM + d0 + ty + i];
        tile[ty + i][tx] = round_tf32(v);
    }
    __syncthreads();
    const int pm = ((tx & 3) << 3) + (tx >> 2);     // perm within the 32-wide d-chunk
    #pragma unroll
    for (int i = 0; i < 32; i += 8)
        wt[(size_t)(e0 + ty + i) * D_DIM + d0 + pm] = tile[tx][ty + i];
}

// ---------------- finalize stats: reduce 64 per-mtile partials ----------------
__global__ void finalize_stats_kernel(const float* __restrict__ bn_w,
                                      const float* __restrict__ bn_b)
{
    const int c = blockIdx.x * 256 + threadIdx.x;
    float s = 0.0f, q = 0.0f;
    #pragma unroll
    for (int k = 0; k < 64; k++) {
        s += g_psum[(size_t)k * N_DIM + c];
        q += g_psq[(size_t)k * N_DIM + c];
    }
    const float inv_b = 1.0f / (float)B_DIM;
    float mean = s * inv_b;
    float var = q * inv_b - mean * mean;
    float rstd = rsqrtf(var + 1e-5f);
    float sc = rstd * bn_w[c];
    g_s[c] = sc;
    g_t[c] = bn_b[c] - mean * sc;
}

// g_bias2f[e] = bias2[e] + sum_d t[p*D+d] * W2[p][d][e]
__global__ void biasfold_kernel(const float* __restrict__ bias2, const float* __restrict__ w2)
{
    const int e = blockIdx.x * 128 + threadIdx.x;
    const int p = e / D_DIM;
    const int el = e % D_DIM;
    const float* wp = w2 + (size_t)p * D_DIM * D_DIM + el;
    const float* tp = g_t + p * D_DIM;
    float c = 0.0f;
    #pragma unroll 8
    for (int d = 0; d < D_DIM; d++)
        c += tp[d] * wp[(size_t)d * D_DIM];
    g_bias2f[e] = bias2[e] + c;
}

// ---------------- launch ----------------
extern "C" void kernel_launch(void* const* d_in, const int* in_sizes, int n_in,
                              void* d_out, int out_size)
{
    (void)in_sizes; (void)n_in; (void)out_size;
    const float* x   = (const float*)d_in[0];
    const float* w1  = (const float*)d_in[1];
    const float* w2  = (const float*)d_in[3];
    const float* b2  = (const float*)d_in[4];
    const float* bnw = (const float*)d_in[5];
    const float* bnb = (const float*)d_in[6];
    const float* g3  = (const float*)d_in[7];
    const float* be3 = (const float*)d_in[8];
    float* out = (float*)d_out;

    cudaFuncSetAttribute(gemm_mma<0>, cudaFuncAttributeMaxDynamicSharedMemorySize, SMEM_BYTES);
    cudaFuncSetAttribute(gemm_mma<1>, cudaFuncAttributeMaxDynamicSharedMemorySize, SMEM_BYTES);

    dim3 ggrid(N_DIM / BN, B_DIM / BM);   // (32, 64)
    dim3 wgrid(D_DIM / 32, D_DIM / 32, P_DIM);
    dim3 wblk(32, 8);

    // 0) prep: x -> g_xp (round+permute); W1 -> g_w1t (transpose+round+permute)
    prep_x_kernel<<<(int)(((size_t)B_DIM * N_DIM / 4) / 256), 256>>>(x);
    prep_w_kernel<false><<<wgrid, wblk>>>(w1, 0);
    // 1) g_h(perm) = x @ bdiag(W1) + fused partial column stats
    gemm_mma<0><<<ggrid, 256, SMEM_BYTES>>>(nullptr, nullptr, nullptr, nullptr);
    // 2) fold BN into (s, t)
    finalize_stats_kernel<<<N_DIM / 256, 256>>>(bnw, bnb);
    // 3) W2 -> g_w2t (transpose+scale+round+permute); g_bias2f = b2 + t@W2
    prep_w_kernel<true><<<wgrid, wblk>>>(w2, 1);
    biasfold_kernel<<<N_DIM / 128, 128>>>(b2, w2);
    // 4) out = gate(g_h @ g_w2t + g_bias2f + x)
    gemm_mma<1><<<ggrid, 256, SMEM_BYTES>>>(x, g3, be3, out);
}